// round 12
// baseline (speedup 1.0000x reference)
#include <cuda_runtime.h>
#include <cuda_bf16.h>
#include <cstdint>

#define H       256
#define NMAX    131072
#define KOCC    8
#define KSUBJ   16
#define OCC     128
#define NLOG    40
#define TM      128
#define THREADS 256
#define NBLK    128
#define MAXT    16
#define AST     528        // bytes per smem row (264 bf16: 256 + 8 pad)

// ---- smem byte offsets ----
#define SM_AH   0                     // A hi: 128 * 528 = 67584
#define SM_AL   67584                 // A lo: 67584
#define SM_BH   135168                // B hi: 40 * 528 = 21120
#define SM_BL   156288                // B lo: 21120
#define SM_BIAS 177408                // 40 floats (pad 192)
#define SM_SP   177600                // 128 ints
#define SM_SSL  178112                // 128 ints
#define SMEM_SZ 178624

// ---- scratch (device globals; no allocation allowed) ----
__device__ int g_bhist[NBLK][OCC];
__device__ int g_bbase[NBLK][OCC];
__device__ int g_occid[NMAX];
__device__ int g_off[OCC];
__device__ int g_cnt[OCC];
__device__ int g_perm[NMAX + OCC * TM];

// ================= prepass (unchanged, proven) =================
__global__ void k_hist(const int* __restrict__ xph, const int* __restrict__ xol, int n) {
    __shared__ int sh[OCC];
    int b = blockIdx.x, tid = threadIdx.x;
    if (tid < OCC) sh[tid] = 0;
    __syncthreads();
    int per = (n + NBLK - 1) / NBLK;
    int s0 = b * per, s1 = min(s0 + per, n);
    for (int i = s0 + tid; i < s1; i += THREADS) {
        int occ = xph[i] * KOCC + xol[i];
        g_occid[i] = occ;
        atomicAdd(&sh[occ], 1);
    }
    __syncthreads();
    if (tid < OCC) g_bhist[b][tid] = sh[tid];
}

__global__ void k_scan() {
    __shared__ int tot[OCC];
    int o = threadIdx.x;
    int s = 0;
    for (int b = 0; b < NBLK; b++) s += g_bhist[b][o];
    tot[o] = s;
    __syncthreads();
    if (o == 0) {
        int run = 0;
        for (int j = 0; j < OCC; j++) {
            g_off[j] = run;
            g_cnt[j] = tot[j];
            run += ((tot[j] + TM - 1) / TM) * TM;
        }
    }
    __syncthreads();
    int run2 = g_off[o];
    for (int b = 0; b < NBLK; b++) { g_bbase[b][o] = run2; run2 += g_bhist[b][o]; }
}

__global__ void k_scatter(int n) {
    __shared__ int cur[OCC];
    int b = blockIdx.x, tid = threadIdx.x;
    if (tid < OCC) cur[tid] = g_bbase[b][tid];
    __syncthreads();
    int per = (n + NBLK - 1) / NBLK;
    int s0 = b * per, s1 = min(s0 + per, n);
    for (int i = s0 + tid; i < s1; i += THREADS) {
        int occ = g_occid[i];
        int pos = atomicAdd(&cur[occ], 1);
        g_perm[pos] = i;
    }
}

// ================= helpers =================
__device__ __forceinline__ uint32_t smem_u32(const void* p) {
    uint32_t a;
    asm("{ .reg .u64 t; cvta.to.shared.u64 t, %1; cvt.u32.u64 %0, t; }" : "=r"(a) : "l"(p));
    return a;
}

// fp32 -> bf16 hi (truncate) + bf16 lo (exact residual, rounded); 4 elems
__device__ __forceinline__ void cvt_store(char* hiB, char* loB, uint32_t off, float4 v) {
    uint32_t u0 = __float_as_uint(v.x), u1 = __float_as_uint(v.y);
    uint32_t u2 = __float_as_uint(v.z), u3 = __float_as_uint(v.w);
    uint2 hv;
    hv.x = __byte_perm(u0, u1, 0x7632);
    hv.y = __byte_perm(u2, u3, 0x7632);
    *(uint2*)(hiB + off) = hv;
    float lx = v.x - __uint_as_float(u0 & 0xFFFF0000u);
    float ly = v.y - __uint_as_float(u1 & 0xFFFF0000u);
    float lz = v.z - __uint_as_float(u2 & 0xFFFF0000u);
    float lw = v.w - __uint_as_float(u3 & 0xFFFF0000u);
    uint2 lv;
    asm("cvt.rn.bf16x2.f32 %0, %1, %2;" : "=r"(lv.x) : "f"(ly), "f"(lx));
    asm("cvt.rn.bf16x2.f32 %0, %1, %2;" : "=r"(lv.y) : "f"(lw), "f"(lz));
    *(uint2*)(loB + off) = lv;
}

__device__ __forceinline__ void mma16816(float* d, const uint32_t* a, const uint32_t* b) {
    asm volatile("mma.sync.aligned.m16n8k16.row.col.f32.bf16.bf16.f32 "
        "{%0,%1,%2,%3}, {%4,%5,%6,%7}, {%8,%9}, {%0,%1,%2,%3};"
        : "+f"(d[0]), "+f"(d[1]), "+f"(d[2]), "+f"(d[3])
        : "r"(a[0]), "r"(a[1]), "r"(a[2]), "r"(a[3]), "r"(b[0]), "r"(b[1]));
}

#define LDSM4(r, a) asm volatile("ldmatrix.sync.aligned.m8n8.x4.shared.b16 {%0,%1,%2,%3}, [%4];" \
    : "=r"((r)[0]), "=r"((r)[1]), "=r"((r)[2]), "=r"((r)[3]) : "r"(a))
#define LDSM2(r, a) asm volatile("ldmatrix.sync.aligned.m8n8.x2.shared.b16 {%0,%1}, [%2];" \
    : "=r"((r)[0]), "=r"((r)[1]) : "r"(a))

#define RED4(v) { v += __shfl_xor_sync(0xFFFFFFFFu, v, 1); v += __shfl_xor_sync(0xFFFFFFFFu, v, 2); }

// ================= main compute: mma.sync bf16-split GEMM =================
extern __shared__ char smem[];

__global__ void __launch_bounds__(THREADS, 1)
k_main(const float* __restrict__ X,
       const float* __restrict__ Wph, const float* __restrict__ bph,
       const float* __restrict__ Wpo, const float* __restrict__ bpo,
       const float* __restrict__ Wos, const float* __restrict__ bos,
       const int* __restrict__ xsl,
       float* __restrict__ out, int n)
{
    const int o  = blockIdx.x;
    const int f  = o >> 3;
    const int ol = o & 7;
    const int cnt = g_cnt[o];
    const int t0  = (int)blockIdx.y * TM;
    if (t0 >= cnt) return;
    const int start = g_off[o] + t0;
    const int rows  = min(TM, cnt - t0);
    const int tid  = threadIdx.x;
    const int w    = tid >> 5;
    const int lane = tid & 31;
    const uint32_t sb = smem_u32(smem);

    int*   sP    = (int*)(smem + SM_SP);
    int*   sSL   = (int*)(smem + SM_SSL);
    float* sBias = (float*)(smem + SM_BIAS);

    if (tid < TM) sP[tid] = (tid < rows) ? g_perm[start + tid] : g_perm[start];
    if (tid < NLOG) {
        float b;
        if (tid < 16)      b = bph[tid];
        else if (tid < 24) b = bpo[f * KOCC + tid - 16];
        else               b = bos[o * KSUBJ + tid - 24];
        sBias[tid] = b;
    }
    __syncthreads();

    // ---- B: 40 x 256 fp32 -> bf16 hi/lo (block-wide) ----
    #pragma unroll
    for (int it = 0; it < 10; it++) {
        int idx = it * THREADS + tid;        // < 2560
        int j = idx >> 6, k4 = idx & 63;
        const float4* src;
        if (j < 16)      src = (const float4*)(Wph + (size_t)j * H);
        else if (j < 24) src = (const float4*)(Wpo + (size_t)(f * KOCC + j - 16) * H);
        else             src = (const float4*)(Wos + (size_t)(o * KSUBJ + j - 24) * H);
        cvt_store(smem + SM_BH, smem + SM_BL, (uint32_t)(j * AST + k4 * 8), src[k4]);
    }
    if (tid < TM) sSL[tid] = xsl[sP[tid]];

    // ---- A: this warp's 16 rows, gather + split (warp-private) ----
    #pragma unroll 4
    for (int i = 0; i < 32; i++) {
        int idx = i * 32 + lane;             // < 1024
        int r = idx >> 6, k4 = idx & 63;
        int row = 16 * w + r;
        float4 x = ((const float4*)(X + (size_t)sP[row] * H))[k4];
        cvt_store(smem + SM_AH, smem + SM_AL, (uint32_t)(row * AST + k4 * 8), x);
    }
    __syncthreads();   // B (and everyone's A) visible

    // ---- mainloop: warp w handles rows 16w..16w+15, all 5 n-tiles ----
    float dM[5][4], dC[5][4];
    #pragma unroll
    for (int nt = 0; nt < 5; nt++)
        #pragma unroll
        for (int j = 0; j < 4; j++) { dM[nt][j] = 0.f; dC[nt][j] = 0.f; }

    const int arow = 16 * w + (lane & 15);
    const int aksh = (lane >> 4) << 3;       // +8 k for upper half-warp
    const int bksh = ((lane >> 3) & 1) << 3;
    const int brow = lane & 7;

    #pragma unroll
    for (int kc = 0; kc < 16; kc++) {
        const int k = kc * 16;
        uint32_t aaddr = sb + SM_AH + (uint32_t)(arow * AST + (k + aksh) * 2);
        uint32_t aH[4], aL[4];
        LDSM4(aH, aaddr);
        LDSM4(aL, aaddr + (SM_AL - SM_AH));
        #pragma unroll
        for (int nt = 0; nt < 5; nt++) {
            uint32_t baddr = sb + SM_BH + (uint32_t)((8 * nt + brow) * AST + (k + bksh) * 2);
            uint32_t bH[2], bL[2];
            LDSM2(bH, baddr);
            LDSM2(bL, baddr + (SM_BL - SM_BH));
            mma16816(dM[nt], aH, bH);
            mma16816(dC[nt], aH, bL);
            mma16816(dC[nt], aL, bH);
        }
    }

    // ---- register softmax epilogue ----
    const int g  = lane >> 2;
    const int q  = lane & 3;
    const int c0 = 2 * q;
    const int tr0 = 16 * w + g, tr1 = tr0 + 8;
    const int sl0 = sSL[tr0], sl1 = sSL[tr1];

    float e[5][4];
    #pragma unroll
    for (int nt = 0; nt < 5; nt++)
        #pragma unroll
        for (int j = 0; j < 4; j++) {
            int col = 8 * nt + c0 + (j & 1);
            e[nt][j] = __expf(dM[nt][j] + dC[nt][j] + sBias[col]);
        }

    float s0a = e[0][0] + e[0][1] + e[1][0] + e[1][1];
    float s0b = e[0][2] + e[0][3] + e[1][2] + e[1][3];
    float s1a = e[2][0] + e[2][1];
    float s1b = e[2][2] + e[2][3];
    float s2a = e[3][0] + e[3][1] + e[4][0] + e[4][1];
    float s2b = e[3][2] + e[3][3] + e[4][2] + e[4][3];

    float pfa = 0.f, pfb = 0.f, poa = 0.f, pob = 0.f, psa = 0.f, psb = 0.f;
    #pragma unroll
    for (int nt = 0; nt < 2; nt++)
        #pragma unroll
        for (int jj = 0; jj < 2; jj++) {
            if (8 * nt + c0 + jj == f) { pfa = e[nt][jj]; pfb = e[nt][jj + 2]; }
        }
    #pragma unroll
    for (int jj = 0; jj < 2; jj++)
        if (c0 + jj == ol) { poa = e[2][jj]; pob = e[2][jj + 2]; }
    #pragma unroll
    for (int nt = 3; nt < 5; nt++)
        #pragma unroll
        for (int jj = 0; jj < 2; jj++) {
            int col = 8 * nt + c0 + jj;
            if (col == 24 + sl0) psa = e[nt][jj];
            if (col == 24 + sl1) psb = e[nt][jj + 2];
        }

    RED4(s0a); RED4(s1a); RED4(s2a); RED4(pfa); RED4(poa); RED4(psa);
    RED4(s0b); RED4(s1b); RED4(s2b); RED4(pfb); RED4(pob); RED4(psb);

    if (q == 0) {
        if (tr0 < rows) {
            int orig = sP[tr0];
            float p1 = pfa / s0a;
            float po = p1 * poa / s1a;
            out[orig]                 = p1;
            out[(size_t)n + orig]     = po;
            out[2 * (size_t)n + orig] = po * psa / s2a;
        }
        if (tr1 < rows) {
            int orig = sP[tr1];
            float p1 = pfb / s0b;
            float po = p1 * pob / s1b;
            out[orig]                 = p1;
            out[(size_t)n + orig]     = po;
            out[2 * (size_t)n + orig] = po * psb / s2b;
        }
    }
}

// ================= launch =================
extern "C" void kernel_launch(void* const* d_in, const int* in_sizes, int n_in,
                              void* d_out, int out_size)
{
    const float* X   = (const float*)d_in[0];
    const float* Wph = (const float*)d_in[1];
    const float* bph = (const float*)d_in[2];
    const float* Wpo = (const float*)d_in[3];
    const float* bpo = (const float*)d_in[4];
    const float* Wos = (const float*)d_in[5];
    const float* bos = (const float*)d_in[6];
    const int*   xph = (const int*)d_in[7];
    const int*   xol = (const int*)d_in[8];
    const int*   xsl = (const int*)d_in[9];
    float* out = (float*)d_out;
    const int n = in_sizes[0] / H;

    k_hist<<<NBLK, THREADS>>>(xph, xol, n);
    k_scan<<<1, OCC>>>();
    k_scatter<<<NBLK, THREADS>>>(n);

    cudaFuncSetAttribute(k_main, cudaFuncAttributeMaxDynamicSharedMemorySize, SMEM_SZ);
    dim3 grid(OCC, MAXT);
    k_main<<<grid, THREADS, SMEM_SZ>>>(X, Wph, bph, Wpo, bpo, Wos, bos, xsl, out, n);
}